// round 15
// baseline (speedup 1.0000x reference)
#include <cuda_runtime.h>
#include <cuda_fp16.h>

#define NF    50
#define DIM   64
#define ATT   64
#define CARDI 10000
#define NPAIR 1225
#define NPAIRP 1232
#define NROWS 2
#define NTHREADS 256
#define MTILE 128
#define NTILES 10
#define NITEMS 40
#define BST   144
#define FSTB  144

// ---- dynamic smem byte offsets (all 16B-aligned) ----
#define OFF_B    0                        // B = W1^T: 64 x 144B          (9216)
#define OFF_F    9216                     // sF: 100 x 144B               (14400)
#define OFF_LP   23616                    // u32 packed logit halves [2][1232]
#define OFF_SM   33472                    // u16 ssum [2][1232]
#define OFF_SIJ  38400                    // ushort sij[1232]
#define OFF_W2F  40864                    // w2 table [2][4][4] words
#define OFF_B1F  40992                    // b1 table [2][4][4] words
#define SMEM_DYN 41120

__device__ __forceinline__ unsigned smem_u32(const void* p) {
    unsigned a;
    asm("{ .reg .u64 t; cvta.to.shared.u64 t, %1; cvt.u32.u64 %0, t; }"
        : "=r"(a) : "l"(p));
    return a;
}
__device__ __forceinline__ unsigned h2pack(float lo, float hi) {
    unsigned r;
    asm("cvt.rn.f16x2.f32 %0, %1, %2;" : "=r"(r) : "f"(hi), "f"(lo));
    return r;
}
__device__ __forceinline__ unsigned hmul2(unsigned a, unsigned b) {
    unsigned r;
    asm("mul.rn.f16x2 %0, %1, %2;" : "=r"(r) : "r"(a), "r"(b));
    return r;
}
__device__ __forceinline__ unsigned hadd2(unsigned a, unsigned b) {
    unsigned r;
    asm("add.rn.f16x2 %0, %1, %2;" : "=r"(r) : "r"(a), "r"(b));
    return r;
}
__device__ __forceinline__ unsigned hmax2(unsigned a, unsigned b) {
    unsigned r;
    asm("max.f16x2 %0, %1, %2;" : "=r"(r) : "r"(a), "r"(b));
    return r;
}
__device__ __forceinline__ unsigned hfma2(unsigned a, unsigned b, unsigned c) {
    unsigned r;
    asm("fma.rn.f16x2 %0, %1, %2, %3;" : "=r"(r) : "r"(a), "r"(b), "r"(c));
    return r;
}
__device__ __forceinline__ unsigned prmt(unsigned a, unsigned b, unsigned s) {
    unsigned r;
    asm("prmt.b32 %0, %1, %2, %3;" : "=r"(r) : "r"(a), "r"(b), "r"(s));
    return r;
}
__device__ __forceinline__ float2 h2f2(unsigned h) {
    float2 f;
    asm("{ .reg .f16 lo, hi; mov.b32 {lo, hi}, %2;\n\t"
        "cvt.f32.f16 %0, lo; cvt.f32.f16 %1, hi; }"
        : "=f"(f.x), "=f"(f.y) : "r"(h));
    return f;
}
__device__ __forceinline__ float h2f(unsigned short h) {
    float f;
    asm("cvt.f32.f16 %0, %1;" : "=f"(f) : "h"(h));
    return f;
}
__device__ __forceinline__ void ldsm4(unsigned& r0, unsigned& r1,
                                      unsigned& r2, unsigned& r3, unsigned addr) {
    asm volatile("ldmatrix.sync.aligned.m8n8.x4.shared.b16 {%0,%1,%2,%3}, [%4];"
                 : "=r"(r0), "=r"(r1), "=r"(r2), "=r"(r3) : "r"(addr));
}
__device__ __forceinline__ void mma_h(unsigned& d0, unsigned& d1,
                                      unsigned a0, unsigned a1, unsigned a2, unsigned a3,
                                      unsigned b0, unsigned b1) {
    asm volatile(
        "mma.sync.aligned.m16n8k16.row.col.f16.f16.f16.f16 "
        "{%0,%1}, {%2,%3,%4,%5}, {%6,%7}, {%0,%1};"
        : "+r"(d0), "+r"(d1)
        : "r"(a0), "r"(a1), "r"(a2), "r"(a3), "r"(b0), "r"(b1));
}

__global__ __launch_bounds__(NTHREADS, 3)
void afm_kernel(const int* __restrict__ x32,
                const float* __restrict__ emb,
                const float* __restrict__ W1,
                const float* __restrict__ b1,
                const float* __restrict__ w2,
                const float* __restrict__ b2,
                const float* __restrict__ lin_w,
                const float* __restrict__ lin_b,
                float* __restrict__ out)
{
    extern __shared__ __align__(16) char sb[];
    unsigned short* sij = (unsigned short*)(sb + OFF_SIJ);
    const unsigned sbase = smem_u32(sb);

    __shared__ float sLinA[NROWS * 64], sRed[32], sM[NROWS];

    const int b0 = blockIdx.x * NROWS, tid = threadIdx.x;
    const int wid = tid >> 5, lane = tid & 31;

    // int32 vs int64 index dtype probe (values < 5e5 -> int64 high words zero)
    const bool is64 = (x32[1] == 0) & (x32[3] == 0) & (x32[5] == 0) & (x32[7] == 0);
    const long long* x64 = (const long long*)x32;

    // ---- Phase A: stage embeddings (2 rows), fragment-permuted f16 ----
    // word w (= k/2) at word offset (w&3)*8 + (w>>3)*2 + ((w>>2)&1)
    for (int q = tid; q < NROWS * NF * DIM / 4; q += NTHREADS) {
        int row = q >> 4, c4 = q & 15;
        int rr = row / NF, fld = row - rr * NF;
        long long xv = is64 ? x64[(long long)(b0 + rr) * NF + fld]
                            : (long long)x32[(b0 + rr) * NF + fld];
        int gidx = (int)xv + fld * CARDI;
        float4 v = ((const float4*)(emb + (long long)gidx * DIM))[c4];
        unsigned w0 = h2pack(v.x, v.y), w1 = h2pack(v.z, v.w);
        unsigned* dst = (unsigned*)(sb + OFF_F + row * FSTB);
        int wa = 2 * c4, wb = 2 * c4 + 1;
        dst[(wa & 3) * 8 + (wa >> 3) * 2 + ((wa >> 2) & 1)] = w0;
        dst[(wb & 3) * 8 + (wb >> 3) * 2 + ((wb >> 2) & 1)] = w1;
    }
    {   // B[n][k] = W1[k][n] f16, row stride 144B
        int n = tid & 63, kg = tid >> 6;
        unsigned u[8];
        #pragma unroll
        for (int e = 0; e < 8; e++) {
            float w0 = W1[(kg * 16 + 2 * e) * ATT + n];
            float w1v = W1[(kg * 16 + 2 * e + 1) * ATT + n];
            u[e] = h2pack(w0, w1v);
        }
        char* dst = sb + OFF_B + n * BST + kg * 32;
        *(uint4*)(dst)      = make_uint4(u[0], u[1], u[2], u[3]);
        *(uint4*)(dst + 16) = make_uint4(u[4], u[5], u[6], u[7]);
    }
    if (tid < 8) {                        // w2/b1 tables: [half][c][j]
        int h = tid >> 2, c = tid & 3;
        unsigned* wt = (unsigned*)(sb + OFF_W2F) + (h * 4 + c) * 4;
        unsigned* bt = (unsigned*)(sb + OFF_B1F) + (h * 4 + c) * 4;
        #pragma unroll
        for (int j = 0; j < 4; j++) {
            int col = h * 32 + j * 8 + 2 * c;
            wt[j] = h2pack(w2[col], w2[col + 1]);
            bt[j] = h2pack(b1[col], b1[col + 1]);
        }
    }
    if (tid < NROWS * 64) {               // linear weights
        int rr = tid >> 6, fld = tid & 63;
        float lv = 0.0f;
        if (fld < NF) {
            long long xv = is64 ? x64[(long long)(b0 + rr) * NF + fld]
                                : (long long)x32[(b0 + rr) * NF + fld];
            lv = lin_w[(int)xv + fld * CARDI];
        }
        sLinA[tid] = lv;
    }
    for (int p = tid; p < NPAIR; p += NTHREADS) {
        int i = (int)((99.0f - sqrtf(9801.0f - 8.0f * (float)p)) * 0.5f);
        i = min(max(i, 0), 48);
        while (i * (99 - i) / 2 > p) --i;
        while ((i + 1) * (98 - i) / 2 <= p) ++i;
        int j = i + 1 + (p - i * (99 - i) / 2);
        sij[p] = (unsigned short)(i | (j << 8));
    }

    const int half = wid & 1;
    const int g    = lane >> 2;
    const int cx   = (lane & 3) * 32;
    const unsigned aBrow = sbase + OFF_B
                         + (half * 32 + (lane >> 4) * 8 + (lane & 7)) * BST
                         + ((lane >> 3) & 1) * 16;
    const unsigned onesf = (lane < 4) ? 0x3C003C00u : 0u;
    __syncthreads();

    // ---- preload B half (32 cols) + w2/b1 fragments ----
    unsigned Bf[4][2][4];
    #pragma unroll
    for (int kk = 0; kk < 4; kk++)
        #pragma unroll
        for (int jp = 0; jp < 2; jp++)
            ldsm4(Bf[kk][jp][0], Bf[kk][jp][1], Bf[kk][jp][2], Bf[kk][jp][3],
                  aBrow + (jp * 16) * BST + kk * 32);
    unsigned w2f[4], b1f[4];
    *(uint4*)w2f = *(const uint4*)(sb + OFF_W2F + (half * 4 + (lane & 3)) * 16);
    *(uint4*)b1f = *(const uint4*)(sb + OFF_B1F + (half * 4 + (lane & 3)) * 16);

    // ---- work items: (row2, tile, rowblock, half); 40 per warp ----
    int rest = wid >> 1;
    #pragma unroll 1
    for (int k = 0; k < NITEMS; k++, rest += 4) {
        int rb = rest & 7;
        int q  = rest >> 3;                   // 0..19
        int r2 = (q >= NTILES) ? 1 : 0;
        int tt = q - r2 * NTILES;
        int pb = tt * MTILE + rb * 16 + g;
        const char* fbase = sb + OFF_F + r2 * NF * FSTB;

        int q1 = min(pb, NPAIR - 1), q2 = min(pb + 8, NPAIR - 1);
        unsigned s1 = sij[q1], s2 = sij[q2];

        const uint4* fi1 = (const uint4*)(fbase + (s1 & 255) * FSTB + cx);
        const uint4* fj1 = (const uint4*)(fbase + (s1 >> 8)  * FSTB + cx);
        const uint4* fi2 = (const uint4*)(fbase + (s2 & 255) * FSTB + cx);
        const uint4* fj2 = (const uint4*)(fbase + (s2 >> 8)  * FSTB + cx);

        unsigned af[4][4];
        {
            uint4 ia = fi1[0], ja = fj1[0], ib = fi2[0], jb = fj2[0];
            af[0][0] = hmul2(ia.x, ja.x); af[0][2] = hmul2(ia.y, ja.y);
            af[1][0] = hmul2(ia.z, ja.z); af[1][2] = hmul2(ia.w, ja.w);
            af[0][1] = hmul2(ib.x, jb.x); af[0][3] = hmul2(ib.y, jb.y);
            af[1][1] = hmul2(ib.z, jb.z); af[1][3] = hmul2(ib.w, jb.w);
            ia = fi1[1]; ja = fj1[1]; ib = fi2[1]; jb = fj2[1];
            af[2][0] = hmul2(ia.x, ja.x); af[2][2] = hmul2(ia.y, ja.y);
            af[3][0] = hmul2(ia.z, ja.z); af[3][2] = hmul2(ia.w, ja.w);
            af[2][1] = hmul2(ib.x, jb.x); af[2][3] = hmul2(ib.y, jb.y);
            af[3][1] = hmul2(ib.z, jb.z); af[3][3] = hmul2(ib.w, jb.w);
        }

        uint2 acc[4];
        #pragma unroll
        for (int j = 0; j < 4; j++) acc[j] = make_uint2(0u, 0u);
        unsigned accS0 = 0u, accS1 = 0u;

        #pragma unroll
        for (int kk = 0; kk < 4; kk++) {
            mma_h(acc[0].x, acc[0].y, af[kk][0], af[kk][1], af[kk][2], af[kk][3],
                  Bf[kk][0][0], Bf[kk][0][1]);
            mma_h(acc[1].x, acc[1].y, af[kk][0], af[kk][1], af[kk][2], af[kk][3],
                  Bf[kk][0][2], Bf[kk][0][3]);
            mma_h(acc[2].x, acc[2].y, af[kk][0], af[kk][1], af[kk][2], af[kk][3],
                  Bf[kk][1][0], Bf[kk][1][1]);
            mma_h(acc[3].x, acc[3].y, af[kk][0], af[kk][1], af[kk][2], af[kk][3],
                  Bf[kk][1][2], Bf[kk][1][3]);
            if (half == 0)
                mma_h(accS0, accS1, af[kk][0], af[kk][1], af[kk][2], af[kk][3],
                      onesf, onesf);
        }

        // partial logits over this warp's 32 cols (bias+relu per-col exact split)
        unsigned phx = 0u, phz = 0u;
        #pragma unroll
        for (int j = 0; j < 4; j++) {
            unsigned hx = hmax2(hadd2(acc[j].x, b1f[j]), 0u);
            unsigned hz = hmax2(hadd2(acc[j].y, b1f[j]), 0u);
            phx = hfma2(hx, w2f[j], phx);
            phz = hfma2(hz, w2f[j], phz);
        }
        unsigned lg  = hadd2(phx, prmt(phx, phx, 0x1032));
        unsigned lg8 = hadd2(phz, prmt(phz, phz, 0x1032));
        unsigned packL = prmt(lg, lg8, 0x5410);
        #pragma unroll
        for (int o = 1; o <= 2; o <<= 1)
            packL = hadd2(packL, __shfl_xor_sync(0xffffffffu, packL, o));

        if ((lane & 3) == 0) {
            char* lpb = sb + OFF_LP + r2 * NPAIRP * 4 + half * 2;
            if (pb < NPAIR)
                *(unsigned short*)(lpb + pb * 4) = (unsigned short)(packL & 0xffff);
            if (pb + 8 < NPAIR)
                *(unsigned short*)(lpb + (pb + 8) * 4) = (unsigned short)(packL >> 16);
            if (half == 0) {
                char* smb = sb + OFF_SM + r2 * NPAIRP * 2;
                if (pb < NPAIR)
                    *(unsigned short*)(smb + pb * 2) = (unsigned short)(accS0 & 0xffff);
                if (pb + 8 < NPAIR)
                    *(unsigned short*)(smb + (pb + 8) * 2) = (unsigned short)(accS1 & 0xffff);
            }
        }
    }
    __syncthreads();

    // ---- softmax + combine: 2 groups of 4 warps, one batch row each ----
    const int grp = wid >> 2;
    const int gtid = tid & 127;
    const unsigned* lp = (const unsigned*)(sb + OFF_LP) + grp * NPAIRP;
    const unsigned short* sm = (const unsigned short*)(sb + OFF_SM) + grp * NPAIRP;

    float m = -1e30f;
    for (int p = gtid; p < NPAIR; p += 128) {
        float2 lf = h2f2(lp[p]);
        m = fmaxf(m, lf.x + lf.y);
    }
    #pragma unroll
    for (int o = 16; o; o >>= 1) m = fmaxf(m, __shfl_xor_sync(0xffffffffu, m, o));
    if (lane == 0) sRed[wid] = m;
    __syncthreads();
    if (gtid == 0)
        sM[grp] = fmaxf(fmaxf(sRed[grp * 4], sRed[grp * 4 + 1]),
                        fmaxf(sRed[grp * 4 + 2], sRed[grp * 4 + 3]));
    __syncthreads();
    const float M = sM[grp];

    float es = 0.0f, ws = 0.0f;
    for (int p = gtid; p < NPAIR; p += 128) {
        float2 lf = h2f2(lp[p]);
        float e = __expf(lf.x + lf.y - M);
        es += e;
        ws = fmaf(e, h2f(sm[p]), ws);
    }
    #pragma unroll
    for (int o = 16; o; o >>= 1) {
        es += __shfl_xor_sync(0xffffffffu, es, o);
        ws += __shfl_xor_sync(0xffffffffu, ws, o);
    }
    if (lane == 0) { sRed[8 + wid] = es; sRed[16 + wid] = ws; }
    __syncthreads();
    if (gtid == 0) {
        float ES = 0.0f, WS = 0.0f;
        #pragma unroll
        for (int w = 0; w < 4; w++) {
            ES += sRed[8 + grp * 4 + w];
            WS += sRed[16 + grp * 4 + w];
        }
        float lin = lin_b[0];
        #pragma unroll
        for (int f = 0; f < NF; f++) lin += sLinA[grp * 64 + f];
        out[b0 + grp] = lin + WS / ES;
    }
}

extern "C" void kernel_launch(void* const* d_in, const int* in_sizes, int n_in,
                              void* d_out, int out_size)
{
    const int*   x     = (const int*)d_in[0];
    const float* emb   = (const float*)d_in[1];
    const float* W1    = (const float*)d_in[2];
    const float* b1    = (const float*)d_in[3];
    const float* w2    = (const float*)d_in[4];
    const float* b2    = (const float*)d_in[5];
    const float* lin_w = (const float*)d_in[6];
    const float* lin_b = (const float*)d_in[7];
    float* out = (float*)d_out;

    static int configured = 0;
    if (!configured) {
        cudaFuncSetAttribute(afm_kernel, cudaFuncAttributeMaxDynamicSharedMemorySize,
                             SMEM_DYN);
        configured = 1;
    }
    afm_kernel<<<out_size / NROWS, NTHREADS, SMEM_DYN>>>(x, emb, W1, b1, w2, b2,
                                                         lin_w, lin_b, out);
}

// round 16
// speedup vs baseline: 1.0072x; 1.0072x over previous
#include <cuda_runtime.h>
#include <cuda_fp16.h>

#define NF    50
#define DIM   64
#define ATT   64
#define CARDI 10000
#define NPAIR 1225
#define NPAIRP 1232
#define NROWS 4
#define NTHREADS 256
#define MTILE 128
#define NTILES 10
#define BST   144
#define FSTB  144

#define ALIGN16(x) (((x) + 15) & ~15)

// ---- dynamic smem byte offsets (all 16B-aligned) ----
#define OFF_B    0                                   // B = W1^T: 64 x 144B
#define OFF_F    (64 * BST)                          // sF: 200 x 144B (4 rows x 50)
#define OFF_LS   ALIGN16(OFF_F + NROWS * NF * FSTB)  // float2 {logit,sum}[4*NPAIRP]
#define OFF_SIJ  ALIGN16(OFF_LS + NROWS * NPAIRP * 8)
#define OFF_W2F  ALIGN16(OFF_SIJ + NPAIRP * 2)
#define OFF_B1F  ALIGN16(OFF_W2F + 128)
#define SMEM_DYN ALIGN16(OFF_B1F + 128)

__device__ __forceinline__ unsigned smem_u32(const void* p) {
    unsigned a;
    asm("{ .reg .u64 t; cvta.to.shared.u64 t, %1; cvt.u32.u64 %0, t; }"
        : "=r"(a) : "l"(p));
    return a;
}
__device__ __forceinline__ unsigned h2pack(float lo, float hi) {
    unsigned r;
    asm("cvt.rn.f16x2.f32 %0, %1, %2;" : "=r"(r) : "f"(hi), "f"(lo));
    return r;
}
__device__ __forceinline__ unsigned hmul2(unsigned a, unsigned b) {
    unsigned r;
    asm("mul.rn.f16x2 %0, %1, %2;" : "=r"(r) : "r"(a), "r"(b));
    return r;
}
__device__ __forceinline__ unsigned hadd2(unsigned a, unsigned b) {
    unsigned r;
    asm("add.rn.f16x2 %0, %1, %2;" : "=r"(r) : "r"(a), "r"(b));
    return r;
}
__device__ __forceinline__ unsigned hmax2(unsigned a, unsigned b) {
    unsigned r;
    asm("max.f16x2 %0, %1, %2;" : "=r"(r) : "r"(a), "r"(b));
    return r;
}
__device__ __forceinline__ unsigned hfma2(unsigned a, unsigned b, unsigned c) {
    unsigned r;
    asm("fma.rn.f16x2 %0, %1, %2, %3;" : "=r"(r) : "r"(a), "r"(b), "r"(c));
    return r;
}
__device__ __forceinline__ unsigned prmt(unsigned a, unsigned b, unsigned s) {
    unsigned r;
    asm("prmt.b32 %0, %1, %2, %3;" : "=r"(r) : "r"(a), "r"(b), "r"(s));
    return r;
}
__device__ __forceinline__ float2 h2f2(unsigned h) {
    float2 f;
    asm("{ .reg .f16 lo, hi; mov.b32 {lo, hi}, %2;\n\t"
        "cvt.f32.f16 %0, lo; cvt.f32.f16 %1, hi; }"
        : "=f"(f.x), "=f"(f.y) : "r"(h));
    return f;
}
__device__ __forceinline__ void ldsm4(unsigned& r0, unsigned& r1,
                                      unsigned& r2, unsigned& r3, unsigned addr) {
    asm volatile("ldmatrix.sync.aligned.m8n8.x4.shared.b16 {%0,%1,%2,%3}, [%4];"
                 : "=r"(r0), "=r"(r1), "=r"(r2), "=r"(r3) : "r"(addr));
}
__device__ __forceinline__ void mma_h(unsigned& d0, unsigned& d1,
                                      unsigned a0, unsigned a1, unsigned a2, unsigned a3,
                                      unsigned b0, unsigned b1) {
    asm volatile(
        "mma.sync.aligned.m16n8k16.row.col.f16.f16.f16.f16 "
        "{%0,%1}, {%2,%3,%4,%5}, {%6,%7}, {%0,%1};"
        : "+r"(d0), "+r"(d1)
        : "r"(a0), "r"(a1), "r"(a2), "r"(a3), "r"(b0), "r"(b1));
}

__global__ __launch_bounds__(NTHREADS, 3)
void afm_kernel(const int* __restrict__ x32,
                const float* __restrict__ emb,
                const float* __restrict__ W1,
                const float* __restrict__ b1,
                const float* __restrict__ w2,
                const float* __restrict__ b2,
                const float* __restrict__ lin_w,
                const float* __restrict__ lin_b,
                float* __restrict__ out)
{
    extern __shared__ __align__(16) char sb[];
    float2* sLS = (float2*)(sb + OFF_LS);
    unsigned short* sij = (unsigned short*)(sb + OFF_SIJ);
    const unsigned sbase = smem_u32(sb);

    __shared__ float sLinA[NROWS * 64], sRed[32], sM[NROWS];

    const int b0 = blockIdx.x * NROWS, tid = threadIdx.x;
    const int wid = tid >> 5, lane = tid & 31;

    // int32 vs int64 index dtype probe (values < 5e5 -> int64 high words zero)
    const bool is64 = (x32[1] == 0) & (x32[3] == 0) & (x32[5] == 0) & (x32[7] == 0);
    const long long* x64 = (const long long*)x32;

    // ---- Phase A: stage embeddings for 4 rows, fragment-permuted f16 ----
    // word w (= k/2) at word offset (w&3)*8 + (w>>3)*2 + ((w>>2)&1)
    for (int q = tid; q < NROWS * NF * DIM / 4; q += NTHREADS) {
        int row = q >> 4, c4 = q & 15;
        int rr = row / NF, fld = row - rr * NF;
        long long xv = is64 ? x64[(long long)(b0 + rr) * NF + fld]
                            : (long long)x32[(b0 + rr) * NF + fld];
        int gidx = (int)xv + fld * CARDI;
        float4 v = ((const float4*)(emb + (long long)gidx * DIM))[c4];
        unsigned w0 = h2pack(v.x, v.y), w1 = h2pack(v.z, v.w);
        unsigned* dst = (unsigned*)(sb + OFF_F + row * FSTB);
        int wa = 2 * c4, wb = 2 * c4 + 1;
        dst[(wa & 3) * 8 + (wa >> 3) * 2 + ((wa >> 2) & 1)] = w0;
        dst[(wb & 3) * 8 + (wb >> 3) * 2 + ((wb >> 2) & 1)] = w1;
    }
    {   // B[n][k] = W1[k][n] f16, row stride 144B
        int n = tid & 63, kg = tid >> 6;
        unsigned u[8];
        #pragma unroll
        for (int e = 0; e < 8; e++) {
            float w0 = W1[(kg * 16 + 2 * e) * ATT + n];
            float w1v = W1[(kg * 16 + 2 * e + 1) * ATT + n];
            u[e] = h2pack(w0, w1v);
        }
        char* dst = sb + OFF_B + n * BST + kg * 32;
        *(uint4*)(dst)      = make_uint4(u[0], u[1], u[2], u[3]);
        *(uint4*)(dst + 16) = make_uint4(u[4], u[5], u[6], u[7]);
    }
    if (tid < 4) {
        int c = tid;
        unsigned* wt = (unsigned*)(sb + OFF_W2F) + c * 8;
        unsigned* bt = (unsigned*)(sb + OFF_B1F) + c * 8;
        #pragma unroll
        for (int j = 0; j < 8; j++) {
            wt[j] = h2pack(w2[8 * j + 2 * c], w2[8 * j + 2 * c + 1]);
            bt[j] = h2pack(b1[8 * j + 2 * c], b1[8 * j + 2 * c + 1]);
        }
    }
    {   // linear weights for 4 rows
        int rr = tid >> 6, fld = tid & 63;
        float lv = 0.0f;
        if (fld < NF) {
            long long xv = is64 ? x64[(long long)(b0 + rr) * NF + fld]
                                : (long long)x32[(b0 + rr) * NF + fld];
            lv = lin_w[(int)xv + fld * CARDI];
        }
        sLinA[tid] = lv;
    }
    for (int p = tid; p < NPAIR; p += NTHREADS) {
        int i = (int)((99.0f - sqrtf(9801.0f - 8.0f * (float)p)) * 0.5f);
        i = min(max(i, 0), 48);
        while (i * (99 - i) / 2 > p) --i;
        while ((i + 1) * (98 - i) / 2 <= p) ++i;
        int j = i + 1 + (p - i * (99 - i) / 2);
        sij[p] = (unsigned short)(i | (j << 8));
    }

    const int m0 = wid * 16;
    const int g  = lane >> 2;
    const int cx = (lane & 3) * 32;
    const unsigned aBrow = sbase + OFF_B + ((lane >> 4) * 8 + (lane & 7)) * BST
                                 + ((lane >> 3) & 1) * 16;
    __syncthreads();

    // ---- resident B fragments for kk=0 only (16 regs) ----
    unsigned Bf0[4][4];
    #pragma unroll
    for (int jp = 0; jp < 4; jp++)
        ldsm4(Bf0[jp][0], Bf0[jp][1], Bf0[jp][2], Bf0[jp][3],
              aBrow + (jp * 16) * BST);

    // ---- pair tiles: 4 rows x 10 tiles, warp-independent ----
    #pragma unroll 1
    for (int r4 = 0; r4 < NROWS; r4++) {
        const char* fbase = sb + OFF_F + r4 * NF * FSTB;
        float2* ls = sLS + r4 * NPAIRP;
        #pragma unroll 1
        for (int tt = 0; tt < NTILES; tt++) {
            int pb = tt * MTILE + m0 + g;
            int q1 = min(pb, NPAIR - 1), q2 = min(pb + 8, NPAIR - 1);
            unsigned s1 = sij[q1], s2 = sij[q2];

            const uint4* fi1 = (const uint4*)(fbase + (s1 & 255) * FSTB + cx);
            const uint4* fj1 = (const uint4*)(fbase + (s1 >> 8)  * FSTB + cx);
            const uint4* fi2 = (const uint4*)(fbase + (s2 & 255) * FSTB + cx);
            const uint4* fj2 = (const uint4*)(fbase + (s2 >> 8)  * FSTB + cx);
            uint4 i1a = fi1[0], i1b = fi1[1];
            uint4 j1a = fj1[0], j1b = fj1[1];
            uint4 i2a = fi2[0], i2b = fi2[1];
            uint4 j2a = fj2[0], j2b = fj2[1];

            unsigned af[4][4];
            af[0][0] = hmul2(i1a.x, j1a.x); af[0][2] = hmul2(i1a.y, j1a.y);
            af[0][1] = hmul2(i2a.x, j2a.x); af[0][3] = hmul2(i2a.y, j2a.y);
            af[1][0] = hmul2(i1a.z, j1a.z); af[1][2] = hmul2(i1a.w, j1a.w);
            af[1][1] = hmul2(i2a.z, j2a.z); af[1][3] = hmul2(i2a.w, j2a.w);
            af[2][0] = hmul2(i1b.x, j1b.x); af[2][2] = hmul2(i1b.y, j1b.y);
            af[2][1] = hmul2(i2b.x, j2b.x); af[2][3] = hmul2(i2b.y, j2b.y);
            af[3][0] = hmul2(i1b.z, j1b.z); af[3][2] = hmul2(i1b.w, j1b.w);
            af[3][1] = hmul2(i2b.z, j2b.z); af[3][3] = hmul2(i2b.w, j2b.w);

            uint2 acc[8];
            #pragma unroll
            for (int j = 0; j < 8; j++) acc[j] = make_uint2(0u, 0u);

            // kk = 0: resident fragments
            #pragma unroll
            for (int jp = 0; jp < 4; jp++) {
                mma_h(acc[2 * jp].x,     acc[2 * jp].y,
                      af[0][0], af[0][1], af[0][2], af[0][3],
                      Bf0[jp][0], Bf0[jp][1]);
                mma_h(acc[2 * jp + 1].x, acc[2 * jp + 1].y,
                      af[0][0], af[0][1], af[0][2], af[0][3],
                      Bf0[jp][2], Bf0[jp][3]);
            }
            // kk = 1..3: stream B fragments from smem
            #pragma unroll
            for (int kk = 1; kk < 4; kk++) {
                unsigned Bt[4][4];
                #pragma unroll
                for (int jp = 0; jp < 4; jp++)
                    ldsm4(Bt[jp][0], Bt[jp][1], Bt[jp][2], Bt[jp][3],
                          aBrow + (jp * 16) * BST + kk * 32);
                #pragma unroll
                for (int jp = 0; jp < 4; jp++) {
                    mma_h(acc[2 * jp].x,     acc[2 * jp].y,
                          af[kk][0], af[kk][1], af[kk][2], af[kk][3],
                          Bt[jp][0], Bt[jp][1]);
                    mma_h(acc[2 * jp + 1].x, acc[2 * jp + 1].y,
                          af[kk][0], af[kk][1], af[kk][2], af[kk][3],
                          Bt[jp][2], Bt[jp][3]);
                }
            }

            // -- ssum from resident A fragments (f16 tree; R13-proven) --
            unsigned sga = hadd2(hadd2(af[0][0], af[0][2]), hadd2(af[1][0], af[1][2]));
            unsigned sgb = hadd2(hadd2(af[2][0], af[2][2]), hadd2(af[3][0], af[3][2]));
            unsigned sg  = hadd2(sga, sgb);
            unsigned s8a = hadd2(hadd2(af[0][1], af[0][3]), hadd2(af[1][1], af[1][3]));
            unsigned s8b = hadd2(hadd2(af[2][1], af[2][3]), hadd2(af[3][1], af[3][3]));
            unsigned sg8 = hadd2(s8a, s8b);
            sg  = hadd2(sg,  prmt(sg,  sg,  0x1032));
            sg8 = hadd2(sg8, prmt(sg8, sg8, 0x1032));
            unsigned packS = prmt(sg, sg8, 0x5410);

            // -- logits: bias+relu+dot(w2) in f16x2 (tables per-tile, broadcast) --
            unsigned w2f[8], b1f[8];
            *(uint4*)&w2f[0] = *(const uint4*)(sb + OFF_W2F + (lane & 3) * 32);
            *(uint4*)&w2f[4] = *(const uint4*)(sb + OFF_W2F + (lane & 3) * 32 + 16);
            *(uint4*)&b1f[0] = *(const uint4*)(sb + OFF_B1F + (lane & 3) * 32);
            *(uint4*)&b1f[4] = *(const uint4*)(sb + OFF_B1F + (lane & 3) * 32 + 16);

            unsigned phx = 0u, phz = 0u;
            #pragma unroll
            for (int j = 0; j < 8; j++) {
                unsigned hx = hmax2(hadd2(acc[j].x, b1f[j]), 0u);
                unsigned hz = hmax2(hadd2(acc[j].y, b1f[j]), 0u);
                phx = hfma2(hx, w2f[j], phx);
                phz = hfma2(hz, w2f[j], phz);
            }
            unsigned lg  = hadd2(phx, prmt(phx, phx, 0x1032));
            unsigned lg8 = hadd2(phz, prmt(phz, phz, 0x1032));
            unsigned packL = prmt(lg, lg8, 0x5410);

            #pragma unroll
            for (int o = 1; o <= 2; o <<= 1) {
                packL = hadd2(packL, __shfl_xor_sync(0xffffffffu, packL, o));
                packS = hadd2(packS, __shfl_xor_sync(0xffffffffu, packS, o));
            }
            if ((lane & 3) == 0) {
                float2 L = h2f2(packL), S = h2f2(packS);
                if (pb < NPAIR)     ls[pb]     = make_float2(L.x, S.x);
                if (pb + 8 < NPAIR) ls[pb + 8] = make_float2(L.y, S.y);
            }
        }
    }
    __syncthreads();

    // ---- softmax + combine: 4 groups of 2 warps, one batch row each ----
    const int grp = wid >> 1;
    const int gtid = tid & 63;
    const float2* ls = sLS + grp * NPAIRP;

    float m = -1e30f;
    for (int p = gtid; p < NPAIR; p += 64) m = fmaxf(m, ls[p].x);
    #pragma unroll
    for (int o = 16; o; o >>= 1) m = fmaxf(m, __shfl_xor_sync(0xffffffffu, m, o));
    if (lane == 0) sRed[wid] = m;
    __syncthreads();
    if (gtid == 0) sM[grp] = fmaxf(sRed[grp * 2], sRed[grp * 2 + 1]);
    __syncthreads();
    const float M = sM[grp];

    float es = 0.0f, ws = 0.0f;
    for (int p = gtid; p < NPAIR; p += 64) {
        float2 v = ls[p];
        float e = __expf(v.x - M);
        es += e;
        ws = fmaf(e, v.y, ws);
    }
    #pragma unroll
    for (int o = 16; o; o >>= 1) {
        es += __shfl_xor_sync(0xffffffffu, es, o);
        ws += __shfl_xor_sync(0xffffffffu, ws, o);
    }
    if (lane == 0) { sRed[8 + wid] = es; sRed[16 + wid] = ws; }
    __syncthreads();
    if (gtid == 0) {
        float ES = sRed[8 + grp * 2] + sRed[8 + grp * 2 + 1];
        float WS = sRed[16 + grp * 2] + sRed[16 + grp * 2 + 1];
        float lin = lin_b[0];
        #pragma unroll
        for (int f = 0; f < NF; f++) lin += sLinA[grp * 64 + f];
        out[b0 + grp] = lin + WS / ES;
    }
}

extern "C" void kernel_launch(void* const* d_in, const int* in_sizes, int n_in,
                              void* d_out, int out_size)
{
    const int*   x     = (const int*)d_in[0];
    const float* emb   = (const float*)d_in[1];
    const float* W1    = (const float*)d_in[2];
    const float* b1    = (const float*)d_in[3];
    const float* w2    = (const float*)d_in[4];
    const float* b2    = (const float*)d_in[5];
    const float* lin_w = (const float*)d_in[6];
    const float* lin_b = (const float*)d_in[7];
    float* out = (float*)d_out;

    static int configured = 0;
    if (!configured) {
        cudaFuncSetAttribute(afm_kernel, cudaFuncAttributeMaxDynamicSharedMemorySize,
                             SMEM_DYN);
        configured = 1;
    }
    afm_kernel<<<out_size / NROWS, NTHREADS, SMEM_DYN>>>(x, emb, W1, b1, w2, b2,
                                                         lin_w, lin_b, out);
}

// round 17
// speedup vs baseline: 1.1727x; 1.1644x over previous
#include <cuda_runtime.h>
#include <cuda_fp16.h>

#define NF    50
#define DIM   64
#define ATT   64
#define CARDI 10000
#define NPAIR 1225
#define NPAIRP 1232
#define NROWS 2
#define NTHREADS 256
#define MTILE 128
#define NTILES 10
#define BST   144
#define FSTB  144

#define ALIGN16(x) (((x) + 15) & ~15)

// ---- dynamic smem byte offsets (all 16B-aligned), total ~46KB -> 3 CTAs/SM ----
#define OFF_B    0                                   // B = W1^T: 64 x 144B
#define OFF_F    (64 * BST)                          // sF: 100 x 144B (2 rows x 50)
#define OFF_LS   ALIGN16(OFF_F + NROWS * NF * FSTB)  // float2 {logit,sum}[2*NPAIRP]
#define OFF_SIJ  ALIGN16(OFF_LS + NROWS * NPAIRP * 8)
#define OFF_W2F  ALIGN16(OFF_SIJ + NPAIRP * 2)
#define OFF_B1F  ALIGN16(OFF_W2F + 128)
#define SMEM_DYN ALIGN16(OFF_B1F + 128)

__device__ __forceinline__ unsigned smem_u32(const void* p) {
    unsigned a;
    asm("{ .reg .u64 t; cvta.to.shared.u64 t, %1; cvt.u32.u64 %0, t; }"
        : "=r"(a) : "l"(p));
    return a;
}
__device__ __forceinline__ unsigned h2pack(float lo, float hi) {
    unsigned r;
    asm("cvt.rn.f16x2.f32 %0, %1, %2;" : "=r"(r) : "f"(hi), "f"(lo));
    return r;
}
__device__ __forceinline__ unsigned hmul2(unsigned a, unsigned b) {
    unsigned r;
    asm("mul.rn.f16x2 %0, %1, %2;" : "=r"(r) : "r"(a), "r"(b));
    return r;
}
__device__ __forceinline__ unsigned hadd2(unsigned a, unsigned b) {
    unsigned r;
    asm("add.rn.f16x2 %0, %1, %2;" : "=r"(r) : "r"(a), "r"(b));
    return r;
}
__device__ __forceinline__ unsigned hmax2(unsigned a, unsigned b) {
    unsigned r;
    asm("max.f16x2 %0, %1, %2;" : "=r"(r) : "r"(a), "r"(b));
    return r;
}
__device__ __forceinline__ unsigned hfma2(unsigned a, unsigned b, unsigned c) {
    unsigned r;
    asm("fma.rn.f16x2 %0, %1, %2, %3;" : "=r"(r) : "r"(a), "r"(b), "r"(c));
    return r;
}
__device__ __forceinline__ unsigned prmt(unsigned a, unsigned b, unsigned s) {
    unsigned r;
    asm("prmt.b32 %0, %1, %2, %3;" : "=r"(r) : "r"(a), "r"(b), "r"(s));
    return r;
}
__device__ __forceinline__ float2 h2f2(unsigned h) {
    float2 f;
    asm("{ .reg .f16 lo, hi; mov.b32 {lo, hi}, %2;\n\t"
        "cvt.f32.f16 %0, lo; cvt.f32.f16 %1, hi; }"
        : "=f"(f.x), "=f"(f.y) : "r"(h));
    return f;
}
__device__ __forceinline__ void ldsm4(unsigned& r0, unsigned& r1,
                                      unsigned& r2, unsigned& r3, unsigned addr) {
    asm volatile("ldmatrix.sync.aligned.m8n8.x4.shared.b16 {%0,%1,%2,%3}, [%4];"
                 : "=r"(r0), "=r"(r1), "=r"(r2), "=r"(r3) : "r"(addr));
}
__device__ __forceinline__ void mma_h(unsigned& d0, unsigned& d1,
                                      unsigned a0, unsigned a1, unsigned a2, unsigned a3,
                                      unsigned b0, unsigned b1) {
    asm volatile(
        "mma.sync.aligned.m16n8k16.row.col.f16.f16.f16.f16 "
        "{%0,%1}, {%2,%3,%4,%5}, {%6,%7}, {%0,%1};"
        : "+r"(d0), "+r"(d1)
        : "r"(a0), "r"(a1), "r"(a2), "r"(a3), "r"(b0), "r"(b1));
}

__global__ __launch_bounds__(NTHREADS, 3)
void afm_kernel(const int* __restrict__ x32,
                const float* __restrict__ emb,
                const float* __restrict__ W1,
                const float* __restrict__ b1,
                const float* __restrict__ w2,
                const float* __restrict__ b2,
                const float* __restrict__ lin_w,
                const float* __restrict__ lin_b,
                float* __restrict__ out)
{
    extern __shared__ __align__(16) char sb[];
    float2* sLS = (float2*)(sb + OFF_LS);
    unsigned short* sij = (unsigned short*)(sb + OFF_SIJ);
    const unsigned sbase = smem_u32(sb);

    __shared__ float sLinA[NROWS * 64], sRed[32], sM[NROWS];

    const int b0 = blockIdx.x * NROWS, tid = threadIdx.x;
    const int wid = tid >> 5, lane = tid & 31;

    // int32 vs int64 index dtype probe (values < 5e5 -> int64 high words zero)
    const bool is64 = (x32[1] == 0) & (x32[3] == 0) & (x32[5] == 0) & (x32[7] == 0);
    const long long* x64 = (const long long*)x32;

    // ---- Phase A: stage embeddings (2 rows), fragment-permuted f16 ----
    // word w (= k/2) at word offset (w&3)*8 + (w>>3)*2 + ((w>>2)&1)
    for (int q = tid; q < NROWS * NF * DIM / 4; q += NTHREADS) {
        int row = q >> 4, c4 = q & 15;
        int rr = row / NF, fld = row - rr * NF;
        long long xv = is64 ? x64[(long long)(b0 + rr) * NF + fld]
                            : (long long)x32[(b0 + rr) * NF + fld];
        int gidx = (int)xv + fld * CARDI;
        float4 v = ((const float4*)(emb + (long long)gidx * DIM))[c4];
        unsigned w0 = h2pack(v.x, v.y), w1 = h2pack(v.z, v.w);
        unsigned* dst = (unsigned*)(sb + OFF_F + row * FSTB);
        int wa = 2 * c4, wb = 2 * c4 + 1;
        dst[(wa & 3) * 8 + (wa >> 3) * 2 + ((wa >> 2) & 1)] = w0;
        dst[(wb & 3) * 8 + (wb >> 3) * 2 + ((wb >> 2) & 1)] = w1;
    }
    {   // B[n][k] = W1[k][n] f16, row stride 144B
        int n = tid & 63, kg = tid >> 6;
        unsigned u[8];
        #pragma unroll
        for (int e = 0; e < 8; e++) {
            float w0 = W1[(kg * 16 + 2 * e) * ATT + n];
            float w1v = W1[(kg * 16 + 2 * e + 1) * ATT + n];
            u[e] = h2pack(w0, w1v);
        }
        char* dst = sb + OFF_B + n * BST + kg * 32;
        *(uint4*)(dst)      = make_uint4(u[0], u[1], u[2], u[3]);
        *(uint4*)(dst + 16) = make_uint4(u[4], u[5], u[6], u[7]);
    }
    if (tid < 4) {
        int c = tid;
        unsigned* wt = (unsigned*)(sb + OFF_W2F) + c * 8;
        unsigned* bt = (unsigned*)(sb + OFF_B1F) + c * 8;
        #pragma unroll
        for (int j = 0; j < 8; j++) {
            wt[j] = h2pack(w2[8 * j + 2 * c], w2[8 * j + 2 * c + 1]);
            bt[j] = h2pack(b1[8 * j + 2 * c], b1[8 * j + 2 * c + 1]);
        }
    }
    if (tid < NROWS * 64) {               // linear weights for 2 rows
        int rr = tid >> 6, fld = tid & 63;
        float lv = 0.0f;
        if (fld < NF) {
            long long xv = is64 ? x64[(long long)(b0 + rr) * NF + fld]
                                : (long long)x32[(b0 + rr) * NF + fld];
            lv = lin_w[(int)xv + fld * CARDI];
        }
        sLinA[tid] = lv;
    }
    for (int p = tid; p < NPAIR; p += NTHREADS) {
        int i = (int)((99.0f - sqrtf(9801.0f - 8.0f * (float)p)) * 0.5f);
        i = min(max(i, 0), 48);
        while (i * (99 - i) / 2 > p) --i;
        while ((i + 1) * (98 - i) / 2 <= p) ++i;
        int j = i + 1 + (p - i * (99 - i) / 2);
        sij[p] = (unsigned short)(i | (j << 8));
    }

    const int m0 = wid * 16;
    const int g  = lane >> 2;
    const int cx = (lane & 3) * 32;
    const unsigned aBrow = sbase + OFF_B + ((lane >> 4) * 8 + (lane & 7)) * BST
                                 + ((lane >> 3) & 1) * 16;
    __syncthreads();

    // ---- resident B fragments for kk=0 only (16 regs) ----
    unsigned Bf0[4][4];
    #pragma unroll
    for (int jp = 0; jp < 4; jp++)
        ldsm4(Bf0[jp][0], Bf0[jp][1], Bf0[jp][2], Bf0[jp][3],
              aBrow + (jp * 16) * BST);

    // ---- pair tiles: 2 rows x 10 tiles, warp-independent ----
    #pragma unroll 1
    for (int r4 = 0; r4 < NROWS; r4++) {
        const char* fbase = sb + OFF_F + r4 * NF * FSTB;
        float2* ls = sLS + r4 * NPAIRP;
        #pragma unroll 1
        for (int tt = 0; tt < NTILES; tt++) {
            int pb = tt * MTILE + m0 + g;
            int q1 = min(pb, NPAIR - 1), q2 = min(pb + 8, NPAIR - 1);
            unsigned s1 = sij[q1], s2 = sij[q2];

            const uint4* fi1 = (const uint4*)(fbase + (s1 & 255) * FSTB + cx);
            const uint4* fj1 = (const uint4*)(fbase + (s1 >> 8)  * FSTB + cx);
            const uint4* fi2 = (const uint4*)(fbase + (s2 & 255) * FSTB + cx);
            const uint4* fj2 = (const uint4*)(fbase + (s2 >> 8)  * FSTB + cx);
            uint4 i1a = fi1[0], i1b = fi1[1];
            uint4 j1a = fj1[0], j1b = fj1[1];
            uint4 i2a = fi2[0], i2b = fi2[1];
            uint4 j2a = fj2[0], j2b = fj2[1];

            unsigned af[4][4];
            af[0][0] = hmul2(i1a.x, j1a.x); af[0][2] = hmul2(i1a.y, j1a.y);
            af[0][1] = hmul2(i2a.x, j2a.x); af[0][3] = hmul2(i2a.y, j2a.y);
            af[1][0] = hmul2(i1a.z, j1a.z); af[1][2] = hmul2(i1a.w, j1a.w);
            af[1][1] = hmul2(i2a.z, j2a.z); af[1][3] = hmul2(i2a.w, j2a.w);
            af[2][0] = hmul2(i1b.x, j1b.x); af[2][2] = hmul2(i1b.y, j1b.y);
            af[2][1] = hmul2(i2b.x, j2b.x); af[2][3] = hmul2(i2b.y, j2b.y);
            af[3][0] = hmul2(i1b.z, j1b.z); af[3][2] = hmul2(i1b.w, j1b.w);
            af[3][1] = hmul2(i2b.z, j2b.z); af[3][3] = hmul2(i2b.w, j2b.w);

            uint2 acc[8];
            #pragma unroll
            for (int j = 0; j < 8; j++) acc[j] = make_uint2(0u, 0u);

            // kk = 0: resident fragments
            #pragma unroll
            for (int jp = 0; jp < 4; jp++) {
                mma_h(acc[2 * jp].x,     acc[2 * jp].y,
                      af[0][0], af[0][1], af[0][2], af[0][3],
                      Bf0[jp][0], Bf0[jp][1]);
                mma_h(acc[2 * jp + 1].x, acc[2 * jp + 1].y,
                      af[0][0], af[0][1], af[0][2], af[0][3],
                      Bf0[jp][2], Bf0[jp][3]);
            }
            // kk = 1..3: stream B fragments from smem
            #pragma unroll
            for (int kk = 1; kk < 4; kk++) {
                unsigned Bt[4][4];
                #pragma unroll
                for (int jp = 0; jp < 4; jp++)
                    ldsm4(Bt[jp][0], Bt[jp][1], Bt[jp][2], Bt[jp][3],
                          aBrow + (jp * 16) * BST + kk * 32);
                #pragma unroll
                for (int jp = 0; jp < 4; jp++) {
                    mma_h(acc[2 * jp].x,     acc[2 * jp].y,
                          af[kk][0], af[kk][1], af[kk][2], af[kk][3],
                          Bt[jp][0], Bt[jp][1]);
                    mma_h(acc[2 * jp + 1].x, acc[2 * jp + 1].y,
                          af[kk][0], af[kk][1], af[kk][2], af[kk][3],
                          Bt[jp][2], Bt[jp][3]);
                }
            }

            // -- ssum from resident A fragments (f16 tree; R13-proven) --
            unsigned sga = hadd2(hadd2(af[0][0], af[0][2]), hadd2(af[1][0], af[1][2]));
            unsigned sgb = hadd2(hadd2(af[2][0], af[2][2]), hadd2(af[3][0], af[3][2]));
            unsigned sg  = hadd2(sga, sgb);
            unsigned s8a = hadd2(hadd2(af[0][1], af[0][3]), hadd2(af[1][1], af[1][3]));
            unsigned s8b = hadd2(hadd2(af[2][1], af[2][3]), hadd2(af[3][1], af[3][3]));
            unsigned sg8 = hadd2(s8a, s8b);
            sg  = hadd2(sg,  prmt(sg,  sg,  0x1032));
            sg8 = hadd2(sg8, prmt(sg8, sg8, 0x1032));
            unsigned packS = prmt(sg, sg8, 0x5410);

            // -- logits: bias+relu+dot(w2) in f16x2 (tables per-tile, broadcast) --
            unsigned w2f[8], b1f[8];
            *(uint4*)&w2f[0] = *(const uint4*)(sb + OFF_W2F + (lane & 3) * 32);
            *(uint4*)&w2f[4] = *(const uint4*)(sb + OFF_W2F + (lane & 3) * 32 + 16);
            *(uint4*)&b1f[0] = *(const uint4*)(sb + OFF_B1F + (lane & 3) * 32);
            *(uint4*)&b1f[4] = *(const uint4*)(sb + OFF_B1F + (lane & 3) * 32 + 16);

            unsigned phx = 0u, phz = 0u;
            #pragma unroll
            for (int j = 0; j < 8; j++) {
                unsigned hx = hmax2(hadd2(acc[j].x, b1f[j]), 0u);
                unsigned hz = hmax2(hadd2(acc[j].y, b1f[j]), 0u);
                phx = hfma2(hx, w2f[j], phx);
                phz = hfma2(hz, w2f[j], phz);
            }
            unsigned lg  = hadd2(phx, prmt(phx, phx, 0x1032));
            unsigned lg8 = hadd2(phz, prmt(phz, phz, 0x1032));
            unsigned packL = prmt(lg, lg8, 0x5410);

            #pragma unroll
            for (int o = 1; o <= 2; o <<= 1) {
                packL = hadd2(packL, __shfl_xor_sync(0xffffffffu, packL, o));
                packS = hadd2(packS, __shfl_xor_sync(0xffffffffu, packS, o));
            }
            if ((lane & 3) == 0) {
                float2 L = h2f2(packL), S = h2f2(packS);
                if (pb < NPAIR)     ls[pb]     = make_float2(L.x, S.x);
                if (pb + 8 < NPAIR) ls[pb + 8] = make_float2(L.y, S.y);
            }
        }
    }
    __syncthreads();

    // ---- softmax + combine: 2 groups of 4 warps, one batch row each ----
    const int grp = wid >> 2;
    const int gtid = tid & 127;
    const float2* ls = sLS + grp * NPAIRP;

    float m = -1e30f;
    for (int p = gtid; p < NPAIR; p += 128) m = fmaxf(m, ls[p].x);
    #pragma unroll
    for (int o = 16; o; o >>= 1) m = fmaxf(m, __shfl_xor_sync(0xffffffffu, m, o));
    if (lane == 0) sRed[wid] = m;
    __syncthreads();
    if (gtid == 0)
        sM[grp] = fmaxf(fmaxf(sRed[grp * 4], sRed[grp * 4 + 1]),
                        fmaxf(sRed[grp * 4 + 2], sRed[grp * 4 + 3]));
    __syncthreads();
    const float M = sM[grp];

    float es = 0.0f, ws = 0.0f;
    for (int p = gtid; p < NPAIR; p += 128) {
        float2 v = ls[p];
        float e = __expf(v.x - M);
        es += e;
        ws = fmaf(e, v.y, ws);
    }
    #pragma unroll
    for (int o = 16; o; o >>= 1) {
        es += __shfl_xor_sync(0xffffffffu, es, o);
        ws += __shfl_xor_sync(0xffffffffu, ws, o);
    }
    if (lane == 0) { sRed[8 + wid] = es; sRed[16 + wid] = ws; }
    __syncthreads();
    if (gtid == 0) {
        float ES = 0.0f, WS = 0.0f;
        #pragma unroll
        for (int w = 0; w < 4; w++) {
            ES += sRed[8 + grp * 4 + w];
            WS += sRed[16 + grp * 4 + w];
        }
        float lin = lin_b[0];
        #pragma unroll
        for (int f = 0; f < NF; f++) lin += sLinA[grp * 64 + f];
        out[b0 + grp] = lin + WS / ES;
    }
}

extern "C" void kernel_launch(void* const* d_in, const int* in_sizes, int n_in,
                              void* d_out, int out_size)
{
    const int*   x     = (const int*)d_in[0];
    const float* emb   = (const float*)d_in[1];
    const float* W1    = (const float*)d_in[2];
    const float* b1    = (const float*)d_in[3];
    const float* w2    = (const float*)d_in[4];
    const float* b2    = (const float*)d_in[5];
    const float* lin_w = (const float*)d_in[6];
    const float* lin_b = (const float*)d_in[7];
    float* out = (float*)d_out;

    static int configured = 0;
    if (!configured) {
        cudaFuncSetAttribute(afm_kernel, cudaFuncAttributeMaxDynamicSharedMemorySize,
                             SMEM_DYN);
        configured = 1;
    }
    afm_kernel<<<out_size / NROWS, NTHREADS, SMEM_DYN>>>(x, emb, W1, b1, w2, b2,
                                                         lin_w, lin_b, out);
}